// round 7
// baseline (speedup 1.0000x reference)
#include <cuda_runtime.h>

// Problem shape (fixed by the dataset)
#define BB 4
#define CC 32
#define HH 64
#define WW 64
#define HWW (HH * WW)      // 4096
#define NW 64

#define THREADS 128
#define PIXPT 2            // pixels per thread (1 f32x2 pair)
#define PIX_PER_BLOCK (THREADS * PIXPT)              // 256
#define BLOCKS_PER_SLICE (HWW / PIX_PER_BLOCK)       // 16
#define GRID (BB * CC * BLOCKS_PER_SLICE)            // 2048

typedef unsigned long long u64;

__device__ __forceinline__ float ex2f(float x) {
    float y;
    asm("ex2.approx.ftz.f32 %0, %1;" : "=f"(y) : "f"(x));
    return y;
}
__device__ __forceinline__ u64 pack2(float lo, float hi) {
    u64 r; asm("mov.b64 %0, {%1, %2};" : "=l"(r) : "f"(lo), "f"(hi)); return r;
}
__device__ __forceinline__ void unpack2(u64 v, float& lo, float& hi) {
    asm("mov.b64 {%0, %1}, %2;" : "=f"(lo), "=f"(hi) : "l"(v));
}
__device__ __forceinline__ u64 fma2(u64 a, u64 b, u64 c) {
    u64 r; asm("fma.rn.f32x2 %0, %1, %2, %3;" : "=l"(r) : "l"(a), "l"(b), "l"(c)); return r;
}
__device__ __forceinline__ u64 mul2(u64 a, u64 b) {
    u64 r; asm("mul.rn.f32x2 %0, %1, %2;" : "=l"(r) : "l"(a), "l"(b)); return r;
}

// exponent(base2) = ka*q + kb*x + kc*y   (kd folded into weights)
//   ka = -log2e/(2*sd), kb = -2*ka*mr, kc = -2*ka*mi
//   wr' = wr * 2^(ka*(mr^2+mi^2)),  wi' likewise

__global__ __launch_bounds__(THREADS, 12)
void cplx_rbf_kernel(const float* __restrict__ xr,
                     const float* __restrict__ xi,
                     const float* __restrict__ wr,
                     const float* __restrict__ wi,
                     const float* __restrict__ br,
                     const float* __restrict__ bi,
                     const float* __restrict__ mur,
                     const float* __restrict__ mui,
                     const float* __restrict__ stddev,
                     float* __restrict__ out)
{
    // pre-duplicated (v,v) f32x2 constants, packed for wide LDS broadcasts
    __shared__ __align__(16) u64 s_kab[NW * 2];  // [2k]=ka  [2k+1]=kb   -> LDS.128
    __shared__ __align__(16) u64 s_kcw[NW * 2];  // [2k]=kc  [2k+1]=wr'  -> LDS.128
    __shared__ u64 s_wi[NW];                     // wi'                  -> LDS.64

    const int slice  = blockIdx.x / BLOCKS_PER_SLICE;   // b*C + c
    const int blk_in = blockIdx.x % BLOCKS_PER_SLICE;
    const int c      = slice % CC;
    const int tid    = threadIdx.x;

    if (tid < NW) {
        const float mr = mur[tid];
        const float mi = mui[tid];
        const float ka = -1.4426950408889634f / (2.0f * stddev[tid]);
        const float kb = -2.0f * ka * mr;
        const float kc = -2.0f * ka * mi;
        const float ew = ex2f(ka * (mr * mr + mi * mi));   // 2^kd
        const float wkr = wr[c * NW + tid] * ew;
        const float wki = wi[c * NW + tid] * ew;
        s_kab[2 * tid]     = pack2(ka, ka);
        s_kab[2 * tid + 1] = pack2(kb, kb);
        s_kcw[2 * tid]     = pack2(kc, kc);
        s_kcw[2 * tid + 1] = pack2(wkr, wkr);
        s_wi[tid]          = pack2(wki, wki);
    }
    __syncthreads();

    const int base = slice * HWW + blk_in * PIX_PER_BLOCK + tid * PIXPT;

    const float2 xr2 = *reinterpret_cast<const float2*>(xr + base);
    const float2 xi2 = *reinterpret_cast<const float2*>(xi + base);

    // pixel pair packed as f32x2
    const u64 xrd = pack2(xr2.x, xr2.y);
    const u64 xid = pack2(xi2.x, xi2.y);
    // q = x^2 + y^2 per pixel
    const u64 qd = fma2(xrd, xrd, mul2(xid, xid));

    u64 srd = 0ull, sid = 0ull;

    const ulonglong2* kab = reinterpret_cast<const ulonglong2*>(s_kab);
    const ulonglong2* kcw = reinterpret_cast<const ulonglong2*>(s_kcw);

    #pragma unroll 16
    for (int k = 0; k < NW; ++k) {
        const ulonglong2 ab = kab[k];     // LDS.128 broadcast
        const ulonglong2 cw = kcw[k];     // LDS.128 broadcast
        const u64 wki = s_wi[k];          // LDS.64  broadcast
        const u64 ka = ab.x, kb = ab.y, kc = cw.x, wkr = cw.y;

        u64 t = fma2(kb, xrd, mul2(ka, qd));
        t = fma2(kc, xid, t);

        float a0, a1;
        unpack2(t, a0, a1);
        const u64 e = pack2(ex2f(a0), ex2f(a1));

        srd = fma2(e, wkr, srd);
        sid = fma2(e, wki, sid);
    }

    const float brc = br[c];
    const float bic = bi[c];

    float sr0, sr1, si0, si1;
    unpack2(srd, sr0, sr1);
    unpack2(sid, si0, si1);

    // Output layout (B,C,H,W,2): interleaved real/imag
    float4 o;
    o.x = sr0 + brc; o.y = si0 + bic;
    o.z = sr1 + brc; o.w = si1 + bic;

    *reinterpret_cast<float4*>(out + (size_t)base * 2) = o;
}

extern "C" void kernel_launch(void* const* d_in, const int* in_sizes, int n_in,
                              void* d_out, int out_size)
{
    const float* xr  = (const float*)d_in[0];
    const float* xi  = (const float*)d_in[1];
    const float* wr  = (const float*)d_in[2];
    const float* wi  = (const float*)d_in[3];
    const float* br  = (const float*)d_in[4];
    const float* bi  = (const float*)d_in[5];
    const float* mur = (const float*)d_in[6];
    const float* mui = (const float*)d_in[7];
    const float* sd  = (const float*)d_in[8];
    float* out       = (float*)d_out;

    cplx_rbf_kernel<<<GRID, THREADS>>>(xr, xi, wr, wi, br, bi, mur, mui, sd, out);
}